// round 2
// baseline (speedup 1.0000x reference)
#include <cuda_runtime.h>
#include <math.h>

// Problem constants
#define N_PIX 4096   // H*W = 64*64
#define M_POOL 1024  // (H/2)*(W/2)
#define CQK_ 64
#define CV_ 256
#define CH_ 512
#define BATCH_ 16

// Scratch (static __device__ globals; allowed per harness rules)
__device__ float g_q[BATCH_ * CQK_ * N_PIX];     // [B,64,4096]
__device__ float g_kp[BATCH_ * CQK_ * M_POOL];   // [B,64,1024]
__device__ float g_vp[BATCH_ * CV_ * M_POOL];    // [B,256,1024]
__device__ float g_attn[BATCH_ * CV_ * N_PIX];   // [B,256,4096]

// ---------------------------------------------------------------------------
// Generic tiled SGEMM: out[b] = W[R,K] @ X[b][K, N_PIX]
//  POOL : epilogue does 2x2 maxpool over the image grid (n-tile of 128 cols
//         == image rows {2*bx, 2*bx+1}), writing [R, M_POOL]
//  RESID: epilogue writes d_out = hidden + gating*(acc + bo[r])
// Block: 256 threads, tile BM=64 x BN=128 x BK=16, microtile 4x8.
// Software-pipelined: next K-tile prefetched into registers during compute.
// ---------------------------------------------------------------------------
template <bool POOL, bool RESID>
__global__ __launch_bounds__(256) void gemm_kernel(
    const float* __restrict__ W, const float* __restrict__ X,
    float* __restrict__ out, int R, int K,
    const float* __restrict__ hidden, const float* __restrict__ bo,
    const float* __restrict__ gating)
{
    constexpr int BM = 64, BN = 128, BK = 16;
    __shared__ float sA[BK][BM + 1];                 // [k][m], pitch 65
    __shared__ float sB[BK][BN];                     // [k][n]
    __shared__ float sC[POOL ? BM : 1][POOL ? BN : 1];

    const int b  = blockIdx.z;
    const int n0 = blockIdx.x * BN;
    const int m0 = blockIdx.y * BM;
    const int tid = threadIdx.x;
    const int tx = tid & 15;       // n-group (8 cols)
    const int ty = tid >> 4;       // m-group (4 rows)

    const float* __restrict__ Xb = X + (size_t)b * K * N_PIX;

    // Per-thread load coordinates
    const int ar = tid >> 4;                 // sA: row 0..63  (4 elems: cols ac..ac+? no)
    const int ac = tid & 15;                 // sA: col (k) 0..15 -> each thread does 4 rows
    const int br = tid >> 5;                 // sB: k-row for float4 loads (idx>>5)
    const int bc4 = tid & 31;                // sB: float4 col 0..31

    float acc[4][8];
#pragma unroll
    for (int i = 0; i < 4; i++)
#pragma unroll
        for (int j = 0; j < 8; j++) acc[i][j] = 0.f;

    // --- prologue: load tile k0 = 0 ---
#pragma unroll
    for (int i = 0; i < 4; i++) {
        int idx = tid + i * 256;
        int r = idx >> 4, c = idx & 15;
        sA[c][r] = W[(size_t)(m0 + r) * K + c];
    }
#pragma unroll
    for (int i = 0; i < 2; i++) {
        int idx = tid + i * 256;             // 512 float4 total
        int r = idx >> 5, c4 = idx & 31;
        const float4 v = *reinterpret_cast<const float4*>(
            &Xb[(size_t)r * N_PIX + n0 + c4 * 4]);
        *reinterpret_cast<float4*>(&sB[r][c4 * 4]) = v;
    }
    __syncthreads();

#pragma unroll 1
    for (int k0 = 0; k0 < K; k0 += BK) {
        const bool has_next = (k0 + BK) < K;
        float rA[4];
        float4 rB[2];
        if (has_next) {
            const int k1 = k0 + BK;
#pragma unroll
            for (int i = 0; i < 4; i++) {
                int idx = tid + i * 256;
                int r = idx >> 4, c = idx & 15;
                rA[i] = W[(size_t)(m0 + r) * K + k1 + c];
            }
#pragma unroll
            for (int i = 0; i < 2; i++) {
                int idx = tid + i * 256;
                int r = idx >> 5, c4 = idx & 31;
                rB[i] = *reinterpret_cast<const float4*>(
                    &Xb[(size_t)(k1 + r) * N_PIX + n0 + c4 * 4]);
            }
        }

#pragma unroll
        for (int k = 0; k < BK; k++) {
            float a0 = sA[k][ty * 4 + 0];
            float a1 = sA[k][ty * 4 + 1];
            float a2 = sA[k][ty * 4 + 2];
            float a3 = sA[k][ty * 4 + 3];
            float bb[8];
#pragma unroll
            for (int j = 0; j < 8; j++) bb[j] = sB[k][tx * 8 + j];
#pragma unroll
            for (int j = 0; j < 8; j++) {
                acc[0][j] = fmaf(a0, bb[j], acc[0][j]);
                acc[1][j] = fmaf(a1, bb[j], acc[1][j]);
                acc[2][j] = fmaf(a2, bb[j], acc[2][j]);
                acc[3][j] = fmaf(a3, bb[j], acc[3][j]);
            }
        }

        if (has_next) {
            __syncthreads();
#pragma unroll
            for (int i = 0; i < 4; i++) {
                int idx = tid + i * 256;
                int r = idx >> 4, c = idx & 15;
                sA[c][r] = rA[i];
            }
#pragma unroll
            for (int i = 0; i < 2; i++) {
                int idx = tid + i * 256;
                int r = idx >> 5, c4 = idx & 31;
                *reinterpret_cast<float4*>(&sB[r][c4 * 4]) = rB[i];
            }
            __syncthreads();
        }
    }

    if (POOL) {
        __syncthreads();   // reuse of sC region is distinct; protect against stragglers
        // Stage tile in smem, then 2x2 maxpool.
        // n-tile covers image rows h0=2*bx and h0+1 (w = 0..63 each).
#pragma unroll
        for (int i = 0; i < 4; i++)
#pragma unroll
            for (int j = 0; j < 8; j++) sC[ty * 4 + i][tx * 8 + j] = acc[i][j];
        __syncthreads();
        const int prow = blockIdx.x;   // pooled row index i (0..31)
#pragma unroll
        for (int i = 0; i < 8; i++) {
            int idx = tid + i * 256;         // 2048 pooled outputs: 64 rows x 32 cols
            int r = idx >> 5, j = idx & 31;
            float v = fmaxf(fmaxf(sC[r][2 * j], sC[r][2 * j + 1]),
                            fmaxf(sC[r][64 + 2 * j], sC[r][64 + 2 * j + 1]));
            int m = prow * 32 + j;
            out[((size_t)(b * R + m0 + r)) * M_POOL + m] = v;
        }
    } else if (RESID) {
        const float g = gating[0];
#pragma unroll
        for (int i = 0; i < 4; i++) {
            int r = m0 + ty * 4 + i;
            float bias = bo[r];
            size_t base = ((size_t)(b * R + r)) * N_PIX + n0 + tx * 8;
            const float4* h4 = reinterpret_cast<const float4*>(hidden + base);
            float4* o4 = reinterpret_cast<float4*>(out + base);
            float4 h0 = h4[0], h1 = h4[1];
            float4 r0, r1;
            r0.x = h0.x + g * (acc[i][0] + bias);
            r0.y = h0.y + g * (acc[i][1] + bias);
            r0.z = h0.z + g * (acc[i][2] + bias);
            r0.w = h0.w + g * (acc[i][3] + bias);
            r1.x = h1.x + g * (acc[i][4] + bias);
            r1.y = h1.y + g * (acc[i][5] + bias);
            r1.z = h1.z + g * (acc[i][6] + bias);
            r1.w = h1.w + g * (acc[i][7] + bias);
            o4[0] = r0; o4[1] = r1;
        }
    } else {
#pragma unroll
        for (int i = 0; i < 4; i++) {
            size_t base = ((size_t)(b * R + m0 + ty * 4 + i)) * N_PIX + n0 + tx * 8;
            float4* o4 = reinterpret_cast<float4*>(out + base);
            float4 r0, r1;
            r0.x = acc[i][0]; r0.y = acc[i][1]; r0.z = acc[i][2]; r0.w = acc[i][3];
            r1.x = acc[i][4]; r1.y = acc[i][5]; r1.z = acc[i][6]; r1.w = acc[i][7];
            o4[0] = r0; o4[1] = r1;
        }
    }
}

// ---------------------------------------------------------------------------
// Flash attention: per block handles one batch b and 64 queries (n-tile).
// Streams over 16 chunks of 64 pooled keys with online softmax.
// O[64 q][256 v] lives in registers: thread t owns query t%64, v-dims
// [64*(t/64) .. +63].
// ---------------------------------------------------------------------------
struct __align__(16) AttnSmem {
    float sQ[64][65];    // [d][q]
    float sK[64][65];    // [d][k]
    float sS[64][65];    // [q][k] scores -> probs
    float sV[256][64];   // [v][k]
    float sRed[4][64];
    float sM[64];
    float sL[64];
    float sAlpha[64];
};

extern __shared__ char attn_smem_raw[];

__global__ __launch_bounds__(256) void attn_kernel()
{
    AttnSmem& s = *reinterpret_cast<AttnSmem*>(attn_smem_raw);
    const int b  = blockIdx.y;
    const int n0 = blockIdx.x * 64;
    const int tid = threadIdx.x;
    const int tq = tid & 15, tk = tid >> 4;    // S-compute mapping (4x4 microtile)
    const int qo = tid & 63, vg = tid >> 6;    // PV / output mapping
    const int row = tid & 63, seg = tid >> 6;  // softmax mapping

    // Load Q tile [64 d][64 q]
#pragma unroll
    for (int i = 0; i < 16; i++) {
        int idx = tid + i * 256;
        int d = idx >> 6, q = idx & 63;
        s.sQ[d][q] = g_q[((size_t)(b * CQK_ + d)) * N_PIX + n0 + q];
    }
    if (tid < 64) { s.sM[tid] = -1e30f; s.sL[tid] = 0.f; }

    float acc[64];
#pragma unroll
    for (int v = 0; v < 64; v++) acc[v] = 0.f;
    __syncthreads();

#pragma unroll 1
    for (int ch = 0; ch < 16; ch++) {
        const int mm0 = ch * 64;
        // Load K chunk [64 d][64 k]
#pragma unroll
        for (int i = 0; i < 16; i++) {
            int idx = tid + i * 256;
            int d = idx >> 6, kk = idx & 63;
            s.sK[d][kk] = g_kp[((size_t)(b * CQK_ + d)) * M_POOL + mm0 + kk];
        }
        // Load V chunk [256 v][64 k]
#pragma unroll 8
        for (int i = 0; i < 64; i++) {
            int idx = tid + i * 256;
            int v = idx >> 6, kk = idx & 63;
            s.sV[v][kk] = g_vp[((size_t)(b * CV_ + v)) * M_POOL + mm0 + kk];
        }
        __syncthreads();

        // S = Q^T K  (each thread: 4q x 4k microtile over 64 dims)
        float sc[4][4];
#pragma unroll
        for (int i = 0; i < 4; i++)
#pragma unroll
            for (int j = 0; j < 4; j++) sc[i][j] = 0.f;
#pragma unroll
        for (int d = 0; d < 64; d++) {
            float a0 = s.sQ[d][tq * 4 + 0];
            float a1 = s.sQ[d][tq * 4 + 1];
            float a2 = s.sQ[d][tq * 4 + 2];
            float a3 = s.sQ[d][tq * 4 + 3];
            float b0 = s.sK[d][tk * 4 + 0];
            float b1 = s.sK[d][tk * 4 + 1];
            float b2 = s.sK[d][tk * 4 + 2];
            float b3 = s.sK[d][tk * 4 + 3];
            sc[0][0] = fmaf(a0, b0, sc[0][0]); sc[0][1] = fmaf(a0, b1, sc[0][1]);
            sc[0][2] = fmaf(a0, b2, sc[0][2]); sc[0][3] = fmaf(a0, b3, sc[0][3]);
            sc[1][0] = fmaf(a1, b0, sc[1][0]); sc[1][1] = fmaf(a1, b1, sc[1][1]);
            sc[1][2] = fmaf(a1, b2, sc[1][2]); sc[1][3] = fmaf(a1, b3, sc[1][3]);
            sc[2][0] = fmaf(a2, b0, sc[2][0]); sc[2][1] = fmaf(a2, b1, sc[2][1]);
            sc[2][2] = fmaf(a2, b2, sc[2][2]); sc[2][3] = fmaf(a2, b3, sc[2][3]);
            sc[3][0] = fmaf(a3, b0, sc[3][0]); sc[3][1] = fmaf(a3, b1, sc[3][1]);
            sc[3][2] = fmaf(a3, b2, sc[3][2]); sc[3][3] = fmaf(a3, b3, sc[3][3]);
        }
#pragma unroll
        for (int i = 0; i < 4; i++)
#pragma unroll
            for (int j = 0; j < 4; j++) s.sS[tq * 4 + i][tk * 4 + j] = sc[i][j];
        __syncthreads();

        // Online softmax: phase 1 — partial max (4 threads/row, 16 cols each)
        float pm = -1e30f;
#pragma unroll
        for (int j = 0; j < 16; j++) pm = fmaxf(pm, s.sS[row][seg * 16 + j]);
        s.sRed[seg][row] = pm;
        __syncthreads();
        // phase 2 — combine, update running max, compute alpha
        if (tid < 64) {
            float mc = fmaxf(fmaxf(s.sRed[0][tid], s.sRed[1][tid]),
                             fmaxf(s.sRed[2][tid], s.sRed[3][tid]));
            float mn = fmaxf(s.sM[tid], mc);
            s.sAlpha[tid] = __expf(s.sM[tid] - mn);
            s.sM[tid] = mn;
        }
        __syncthreads();
        // phase 3 — exponentiate in place, partial sums
        {
            float mn = s.sM[row];
            float ps = 0.f;
#pragma unroll
            for (int j = 0; j < 16; j++) {
                float p = __expf(s.sS[row][seg * 16 + j] - mn);
                s.sS[row][seg * 16 + j] = p;
                ps += p;
            }
            s.sRed[seg][row] = ps;
        }
        __syncthreads();
        // phase 4 — update running denominator
        if (tid < 64) {
            s.sL[tid] = s.sL[tid] * s.sAlpha[tid] +
                        (s.sRed[0][tid] + s.sRed[1][tid] + s.sRed[2][tid] + s.sRed[3][tid]);
        }

        // Rescale accumulators and accumulate P @ V
        float alpha = s.sAlpha[qo];
#pragma unroll
        for (int v = 0; v < 64; v++) acc[v] *= alpha;

#pragma unroll 1
        for (int k0 = 0; k0 < 64; k0 += 8) {
            float p[8];
#pragma unroll
            for (int j = 0; j < 8; j++) p[j] = s.sS[qo][k0 + j];
#pragma unroll 16
            for (int v = 0; v < 64; v++) {
                const float4* vr = reinterpret_cast<const float4*>(&s.sV[vg * 64 + v][k0]);
                float4 v0 = vr[0], v1 = vr[1];
                float t0 = fmaf(p[0], v0.x, fmaf(p[1], v0.y, fmaf(p[2], v0.z, p[3] * v0.w)));
                float t1 = fmaf(p[4], v1.x, fmaf(p[5], v1.y, fmaf(p[6], v1.z, p[7] * v1.w)));
                acc[v] += t0 + t1;
            }
        }
        __syncthreads();  // protect sK/sV/sS/sL before next chunk
    }

    // Finalize and write attn[b, v, n]
    float inv = 1.f / s.sL[qo];
#pragma unroll 16
    for (int v = 0; v < 64; v++) {
        g_attn[((size_t)(b * CV_ + vg * 64 + v)) * N_PIX + n0 + qo] = acc[v] * inv;
    }
}

// ---------------------------------------------------------------------------
// Host launcher
// Inputs (metadata order): hidden, Wq, Wk, Wv, Wo, bo, gating
// ---------------------------------------------------------------------------
extern "C" void kernel_launch(void* const* d_in, const int* in_sizes, int n_in,
                              void* d_out, int out_size)
{
    const float* hidden = (const float*)d_in[0];
    const float* Wq = (const float*)d_in[1];
    const float* Wk = (const float*)d_in[2];
    const float* Wv = (const float*)d_in[3];
    const float* Wo = (const float*)d_in[4];
    const float* bo = (const float*)d_in[5];
    const float* gating = (const float*)d_in[6];
    float* out = (float*)d_out;

    float *pq = nullptr, *pkp = nullptr, *pvp = nullptr, *pattn = nullptr;
    cudaGetSymbolAddress((void**)&pq, g_q);
    cudaGetSymbolAddress((void**)&pkp, g_kp);
    cudaGetSymbolAddress((void**)&pvp, g_vp);
    cudaGetSymbolAddress((void**)&pattn, g_attn);

    dim3 blk(256);

    // q = Wq @ x                         [B,64,4096]
    gemm_kernel<false, false><<<dim3(32, 1, BATCH_), blk>>>(
        Wq, hidden, pq, CQK_, CH_, nullptr, nullptr, nullptr);
    // kp = pool2(Wk @ x)                 [B,64,1024]
    gemm_kernel<true, false><<<dim3(32, 1, BATCH_), blk>>>(
        Wk, hidden, pkp, CQK_, CH_, nullptr, nullptr, nullptr);
    // vp = pool2(Wv @ x)                 [B,256,1024]
    gemm_kernel<true, false><<<dim3(32, 4, BATCH_), blk>>>(
        Wv, hidden, pvp, CV_, CH_, nullptr, nullptr, nullptr);

    // attn = softmax(q^T kp) applied to vp   [B,256,4096]
    cudaFuncSetAttribute(attn_kernel, cudaFuncAttributeMaxDynamicSharedMemorySize,
                         (int)sizeof(AttnSmem));
    attn_kernel<<<dim3(64, BATCH_), blk, sizeof(AttnSmem)>>>();

    // out = hidden + gating * (Wo @ attn + bo)
    gemm_kernel<false, true><<<dim3(32, 8, BATCH_), blk>>>(
        Wo, pattn, out, CH_, CV_, hidden, bo, gating);
}

// round 3
// speedup vs baseline: 1.6083x; 1.6083x over previous
#include <cuda_runtime.h>
#include <math.h>

typedef unsigned long long u64;

// Problem constants
#define N_PIX 4096   // H*W = 64*64
#define M_POOL 1024  // (H/2)*(W/2)
#define CQK_ 64
#define CV_ 256
#define CH_ 512
#define BATCH_ 16

// Scratch (static __device__ globals; allowed per harness rules)
__device__ float g_q[BATCH_ * CQK_ * N_PIX];     // [B,64,4096]
__device__ float g_kp[BATCH_ * CQK_ * M_POOL];   // [B,64,1024]  (d-major)
__device__ float g_vp[BATCH_ * M_POOL * CV_];    // [B,1024,256] (m-major, TRANSPOSED)
__device__ float g_attn[BATCH_ * CV_ * N_PIX];   // [B,256,4096]

// ---- packed f32x2 helpers (Blackwell FFMA2 path) ----
__device__ __forceinline__ u64 pack2(float lo, float hi) {
    u64 r; asm("mov.b64 %0, {%1, %2};" : "=l"(r) : "f"(lo), "f"(hi)); return r;
}
__device__ __forceinline__ void unpack2(u64 v, float& lo, float& hi) {
    asm("mov.b64 {%0, %1}, %2;" : "=f"(lo), "=f"(hi) : "l"(v));
}
__device__ __forceinline__ u64 fma2(u64 a, u64 b, u64 c) {
    u64 d; asm("fma.rn.f32x2 %0, %1, %2, %3;" : "=l"(d) : "l"(a), "l"(b), "l"(c)); return d;
}
__device__ __forceinline__ u64 mul2(u64 a, u64 b) {
    u64 d; asm("mul.rn.f32x2 %0, %1, %2;" : "=l"(d) : "l"(a), "l"(b)); return d;
}

// ---------------------------------------------------------------------------
// Tiled SGEMM: out[b] = W[R,K] @ X[b][K, 4096]
//  POOL   : epilogue 2x2-maxpools the image tile (BN=128 cols == 2 image rows)
//  TRANSP : pooled output written m-major [B, M_POOL, R] (for V)
//  RESID  : epilogue writes d_out = hidden + gating*(acc + bo[r])
// Block 256 thr, tile 64x128x16, microtile 4x8, FFMA2 pairs over n.
// Register-prefetch software pipeline on global loads.
// ---------------------------------------------------------------------------
template <bool POOL, bool RESID, bool TRANSP>
__global__ __launch_bounds__(256) void gemm_kernel(
    const float* __restrict__ W, const float* __restrict__ X,
    float* __restrict__ out, int R, int K,
    const float* __restrict__ hidden, const float* __restrict__ bo,
    const float* __restrict__ gating)
{
    constexpr int BN = 128, BK = 16;
    __shared__ float sA[BK][68];                   // [k][m], pitch 68 (16B-aligned rows)
    __shared__ float sB[BK][BN];                   // [k][n]
    __shared__ float sC[POOL ? 64 : 1][POOL ? 129 : 1];

    const int b  = blockIdx.z;
    const int n0 = blockIdx.x * BN;
    const int m0 = blockIdx.y * 64;
    const int tid = threadIdx.x;
    const int tx = tid & 15;       // n-group (8 cols)
    const int ty = tid >> 4;       // m-group (4 rows)

    const float* __restrict__ Xb = X + (size_t)b * K * N_PIX;

    u64 acc2[4][4];
#pragma unroll
    for (int i = 0; i < 4; i++)
#pragma unroll
        for (int j = 0; j < 4; j++) acc2[i][j] = 0ull;

    // --- prologue: load tile k0 = 0 ---
#pragma unroll
    for (int i = 0; i < 4; i++) {
        int idx = tid + i * 256;
        int r = idx >> 4, c = idx & 15;
        sA[c][r] = W[(size_t)(m0 + r) * K + c];
    }
#pragma unroll
    for (int i = 0; i < 2; i++) {
        int idx = tid + i * 256;
        int r = idx >> 5, c4 = idx & 31;
        *reinterpret_cast<float4*>(&sB[r][c4 * 4]) =
            *reinterpret_cast<const float4*>(&Xb[(size_t)r * N_PIX + n0 + c4 * 4]);
    }
    __syncthreads();

#pragma unroll 1
    for (int k0 = 0; k0 < K; k0 += BK) {
        const bool has_next = (k0 + BK) < K;
        float rA[4];
        float4 rB[2];
        if (has_next) {
            const int k1 = k0 + BK;
#pragma unroll
            for (int i = 0; i < 4; i++) {
                int idx = tid + i * 256;
                int r = idx >> 4, c = idx & 15;
                rA[i] = W[(size_t)(m0 + r) * K + k1 + c];
            }
#pragma unroll
            for (int i = 0; i < 2; i++) {
                int idx = tid + i * 256;
                int r = idx >> 5, c4 = idx & 31;
                rB[i] = *reinterpret_cast<const float4*>(
                    &Xb[(size_t)(k1 + r) * N_PIX + n0 + c4 * 4]);
            }
        }

#pragma unroll
        for (int k = 0; k < BK; k++) {
            float4 av = *reinterpret_cast<const float4*>(&sA[k][ty * 4]);
            u64 a0 = pack2(av.x, av.x);
            u64 a1 = pack2(av.y, av.y);
            u64 a2 = pack2(av.z, av.z);
            u64 a3 = pack2(av.w, av.w);
            u64 b2[4];
#pragma unroll
            for (int j = 0; j < 4; j++)
                b2[j] = *reinterpret_cast<const u64*>(&sB[k][tx * 8 + 2 * j]);
#pragma unroll
            for (int j = 0; j < 4; j++) {
                acc2[0][j] = fma2(a0, b2[j], acc2[0][j]);
                acc2[1][j] = fma2(a1, b2[j], acc2[1][j]);
                acc2[2][j] = fma2(a2, b2[j], acc2[2][j]);
                acc2[3][j] = fma2(a3, b2[j], acc2[3][j]);
            }
        }

        if (has_next) {
            __syncthreads();
#pragma unroll
            for (int i = 0; i < 4; i++) {
                int idx = tid + i * 256;
                int r = idx >> 4, c = idx & 15;
                sA[c][r] = rA[i];
            }
#pragma unroll
            for (int i = 0; i < 2; i++) {
                int idx = tid + i * 256;
                int r = idx >> 5, c4 = idx & 31;
                *reinterpret_cast<float4*>(&sB[r][c4 * 4]) = rB[i];
            }
            __syncthreads();
        }
    }

    // Unpack accumulators
    float acc[4][8];
#pragma unroll
    for (int i = 0; i < 4; i++)
#pragma unroll
        for (int j = 0; j < 4; j++) unpack2(acc2[i][j], acc[i][2 * j], acc[i][2 * j + 1]);

    if (POOL) {
        __syncthreads();
#pragma unroll
        for (int i = 0; i < 4; i++)
#pragma unroll
            for (int j = 0; j < 8; j++) sC[ty * 4 + i][tx * 8 + j] = acc[i][j];
        __syncthreads();
        const int prow = blockIdx.x;   // pooled image row (0..31)
        if (TRANSP) {
            // out[b][m][R]: consecutive threads -> consecutive channel v (coalesced)
#pragma unroll
            for (int i = 0; i < 8; i++) {
                int idx = tid + i * 256;           // 2048 = 64 v x 32 m
                int v = idx & 63, mj = idx >> 6;
                float val = fmaxf(fmaxf(sC[v][2 * mj], sC[v][2 * mj + 1]),
                                  fmaxf(sC[v][64 + 2 * mj], sC[v][64 + 2 * mj + 1]));
                int m = prow * 32 + mj;
                out[((size_t)b * M_POOL + m) * CV_ + m0 + v] = val;
            }
        } else {
#pragma unroll
            for (int i = 0; i < 8; i++) {
                int idx = tid + i * 256;           // 2048 = 64 r x 32 m
                int r = idx >> 5, j = idx & 31;
                float val = fmaxf(fmaxf(sC[r][2 * j], sC[r][2 * j + 1]),
                                  fmaxf(sC[r][64 + 2 * j], sC[r][64 + 2 * j + 1]));
                int m = prow * 32 + j;
                out[((size_t)(b * R + m0 + r)) * M_POOL + m] = val;
            }
        }
    } else if (RESID) {
        const float g = gating[0];
#pragma unroll
        for (int i = 0; i < 4; i++) {
            int r = m0 + ty * 4 + i;
            float bias = bo[r];
            size_t base = ((size_t)(b * R + r)) * N_PIX + n0 + tx * 8;
            const float4* h4 = reinterpret_cast<const float4*>(hidden + base);
            float4* o4 = reinterpret_cast<float4*>(out + base);
            float4 h0 = h4[0], h1 = h4[1];
            float4 r0, r1;
            r0.x = h0.x + g * (acc[i][0] + bias);
            r0.y = h0.y + g * (acc[i][1] + bias);
            r0.z = h0.z + g * (acc[i][2] + bias);
            r0.w = h0.w + g * (acc[i][3] + bias);
            r1.x = h1.x + g * (acc[i][4] + bias);
            r1.y = h1.y + g * (acc[i][5] + bias);
            r1.z = h1.z + g * (acc[i][6] + bias);
            r1.w = h1.w + g * (acc[i][7] + bias);
            o4[0] = r0; o4[1] = r1;
        }
    } else {
#pragma unroll
        for (int i = 0; i < 4; i++) {
            size_t base = ((size_t)(b * R + m0 + ty * 4 + i)) * N_PIX + n0 + tx * 8;
            float4* o4 = reinterpret_cast<float4*>(out + base);
            float4 r0, r1;
            r0.x = acc[i][0]; r0.y = acc[i][1]; r0.z = acc[i][2]; r0.w = acc[i][3];
            r1.x = acc[i][4]; r1.y = acc[i][5]; r1.z = acc[i][6]; r1.w = acc[i][7];
            o4[0] = r0; o4[1] = r1;
        }
    }
}

// ---------------------------------------------------------------------------
// Flash attention: block = (batch b, 64 queries). 16 chunks of 64 keys,
// online softmax. S kept TRANSPOSED [k][q]; V staged TRANSPOSED [k][v] so the
// PV product is a conflict-free register-tiled GEMM (8q x 8v per thread).
// ---------------------------------------------------------------------------
struct __align__(16) AttnSmem {
    float sQ[64][68];    // [d][q]
    float sK[64][68];    // [d][k]
    float sS[64][68];    // [k][q]  scores -> probs (transposed)
    float sV[64][260];   // [k][v]
    float sRed[4][64];
    float sM[64];
    float sL[64];
    float sAlpha[64];
};

extern __shared__ char attn_smem_raw[];

__global__ __launch_bounds__(256) void attn_kernel()
{
    AttnSmem& s = *reinterpret_cast<AttnSmem*>(attn_smem_raw);
    const int b  = blockIdx.y;
    const int n0 = blockIdx.x * 64;
    const int tid = threadIdx.x;
    const int tq = tid & 15, tk = tid >> 4;    // S-compute mapping (4q x 4k)
    const int tq2 = tid & 7, tv = tid >> 3;    // PV mapping (8q x 8v): 8 x 32 groups
    const int row = tid & 63, seg = tid >> 6;  // softmax mapping

    // Load Q tile [64 d][64 q] (float4)
#pragma unroll
    for (int i = 0; i < 4; i++) {
        int idx = tid + i * 256;
        int d = idx >> 4, q4 = idx & 15;
        *reinterpret_cast<float4*>(&s.sQ[d][q4 * 4]) =
            *reinterpret_cast<const float4*>(&g_q[((size_t)(b * CQK_ + d)) * N_PIX + n0 + q4 * 4]);
    }
    if (tid < 64) { s.sM[tid] = -1e30f; s.sL[tid] = 0.f; }

    u64 acc2[8][4];      // [q][v-pair]
#pragma unroll
    for (int i = 0; i < 8; i++)
#pragma unroll
        for (int j = 0; j < 4; j++) acc2[i][j] = 0ull;
    __syncthreads();

#pragma unroll 1
    for (int ch = 0; ch < 16; ch++) {
        const int mm0 = ch * 64;
        // Load K chunk [64 d][64 k] (float4)
#pragma unroll
        for (int i = 0; i < 4; i++) {
            int idx = tid + i * 256;
            int d = idx >> 4, k4 = idx & 15;
            *reinterpret_cast<float4*>(&s.sK[d][k4 * 4]) =
                *reinterpret_cast<const float4*>(&g_kp[((size_t)(b * CQK_ + d)) * M_POOL + mm0 + k4 * 4]);
        }
        // Load V chunk [64 k][256 v] from m-major g_vp (float4, coalesced, conflict-free)
#pragma unroll
        for (int i = 0; i < 16; i++) {
            int idx = tid + i * 256;
            int kk = idx >> 6, v4 = idx & 63;
            *reinterpret_cast<float4*>(&s.sV[kk][v4 * 4]) =
                *reinterpret_cast<const float4*>(&g_vp[((size_t)b * M_POOL + mm0 + kk) * CV_ + v4 * 4]);
        }
        __syncthreads();

        // S = Q^T K  (4q x 4k per thread, FFMA2 pairs over k)
        {
            u64 sc2[4][2];
#pragma unroll
            for (int i = 0; i < 4; i++) { sc2[i][0] = 0ull; sc2[i][1] = 0ull; }
#pragma unroll 8
            for (int d = 0; d < 64; d++) {
                float4 a = *reinterpret_cast<const float4*>(&s.sQ[d][tq * 4]);
                u64 b0 = *reinterpret_cast<const u64*>(&s.sK[d][tk * 4]);
                u64 b1 = *reinterpret_cast<const u64*>(&s.sK[d][tk * 4 + 2]);
                u64 a0 = pack2(a.x, a.x), a1 = pack2(a.y, a.y);
                u64 a2 = pack2(a.z, a.z), a3 = pack2(a.w, a.w);
                sc2[0][0] = fma2(a0, b0, sc2[0][0]); sc2[0][1] = fma2(a0, b1, sc2[0][1]);
                sc2[1][0] = fma2(a1, b0, sc2[1][0]); sc2[1][1] = fma2(a1, b1, sc2[1][1]);
                sc2[2][0] = fma2(a2, b0, sc2[2][0]); sc2[2][1] = fma2(a2, b1, sc2[2][1]);
                sc2[3][0] = fma2(a3, b0, sc2[3][0]); sc2[3][1] = fma2(a3, b1, sc2[3][1]);
            }
            // write scores transposed: sS[k][q]
#pragma unroll
            for (int i = 0; i < 4; i++)
#pragma unroll
                for (int jp = 0; jp < 2; jp++) {
                    float lo, hi;
                    unpack2(sc2[i][jp], lo, hi);
                    s.sS[tk * 4 + 2 * jp][tq * 4 + i] = lo;
                    s.sS[tk * 4 + 2 * jp + 1][tq * 4 + i] = hi;
                }
        }
        __syncthreads();

        // Online softmax (reductions now run down sS columns: conflict-free)
        float pm = -1e30f;
#pragma unroll
        for (int j = 0; j < 16; j++) pm = fmaxf(pm, s.sS[seg * 16 + j][row]);
        s.sRed[seg][row] = pm;
        __syncthreads();
        if (tid < 64) {
            float mc = fmaxf(fmaxf(s.sRed[0][tid], s.sRed[1][tid]),
                             fmaxf(s.sRed[2][tid], s.sRed[3][tid]));
            float mn = fmaxf(s.sM[tid], mc);
            s.sAlpha[tid] = __expf(s.sM[tid] - mn);
            s.sM[tid] = mn;
        }
        __syncthreads();
        {
            float mn = s.sM[row];
            float ps = 0.f;
#pragma unroll
            for (int j = 0; j < 16; j++) {
                float p = __expf(s.sS[seg * 16 + j][row] - mn);
                s.sS[seg * 16 + j][row] = p;
                ps += p;
            }
            s.sRed[seg][row] = ps;
        }
        __syncthreads();
        if (tid < 64) {
            s.sL[tid] = s.sL[tid] * s.sAlpha[tid] +
                        (s.sRed[0][tid] + s.sRed[1][tid] + s.sRed[2][tid] + s.sRed[3][tid]);
        }

        // Rescale accumulators, then O += P^T V  (8q x 8v, FFMA2 pairs over v)
        {
            u64 ap[8];
#pragma unroll
            for (int i = 0; i < 8; i++) {
                float a = s.sAlpha[tq2 * 8 + i];
                ap[i] = pack2(a, a);
            }
#pragma unroll
            for (int i = 0; i < 8; i++)
#pragma unroll
                for (int j = 0; j < 4; j++) acc2[i][j] = mul2(acc2[i][j], ap[i]);

#pragma unroll 4
            for (int k = 0; k < 64; k++) {
                float4 p0 = *reinterpret_cast<const float4*>(&s.sS[k][tq2 * 8]);
                float4 p1 = *reinterpret_cast<const float4*>(&s.sS[k][tq2 * 8 + 4]);
                u64 v0 = *reinterpret_cast<const u64*>(&s.sV[k][tv * 8]);
                u64 v1 = *reinterpret_cast<const u64*>(&s.sV[k][tv * 8 + 2]);
                u64 v2 = *reinterpret_cast<const u64*>(&s.sV[k][tv * 8 + 4]);
                u64 v3 = *reinterpret_cast<const u64*>(&s.sV[k][tv * 8 + 6]);
                u64 pp;
                pp = pack2(p0.x, p0.x);
                acc2[0][0] = fma2(pp, v0, acc2[0][0]); acc2[0][1] = fma2(pp, v1, acc2[0][1]);
                acc2[0][2] = fma2(pp, v2, acc2[0][2]); acc2[0][3] = fma2(pp, v3, acc2[0][3]);
                pp = pack2(p0.y, p0.y);
                acc2[1][0] = fma2(pp, v0, acc2[1][0]); acc2[1][1] = fma2(pp, v1, acc2[1][1]);
                acc2[1][2] = fma2(pp, v2, acc2[1][2]); acc2[1][3] = fma2(pp, v3, acc2[1][3]);
                pp = pack2(p0.z, p0.z);
                acc2[2][0] = fma2(pp, v0, acc2[2][0]); acc2[2][1] = fma2(pp, v1, acc2[2][1]);
                acc2[2][2] = fma2(pp, v2, acc2[2][2]); acc2[2][3] = fma2(pp, v3, acc2[2][3]);
                pp = pack2(p0.w, p0.w);
                acc2[3][0] = fma2(pp, v0, acc2[3][0]); acc2[3][1] = fma2(pp, v1, acc2[3][1]);
                acc2[3][2] = fma2(pp, v2, acc2[3][2]); acc2[3][3] = fma2(pp, v3, acc2[3][3]);
                pp = pack2(p1.x, p1.x);
                acc2[4][0] = fma2(pp, v0, acc2[4][0]); acc2[4][1] = fma2(pp, v1, acc2[4][1]);
                acc2[4][2] = fma2(pp, v2, acc2[4][2]); acc2[4][3] = fma2(pp, v3, acc2[4][3]);
                pp = pack2(p1.y, p1.y);
                acc2[5][0] = fma2(pp, v0, acc2[5][0]); acc2[5][1] = fma2(pp, v1, acc2[5][1]);
                acc2[5][2] = fma2(pp, v2, acc2[5][2]); acc2[5][3] = fma2(pp, v3, acc2[5][3]);
                pp = pack2(p1.z, p1.z);
                acc2[6][0] = fma2(pp, v0, acc2[6][0]); acc2[6][1] = fma2(pp, v1, acc2[6][1]);
                acc2[6][2] = fma2(pp, v2, acc2[6][2]); acc2[6][3] = fma2(pp, v3, acc2[6][3]);
                pp = pack2(p1.w, p1.w);
                acc2[7][0] = fma2(pp, v0, acc2[7][0]); acc2[7][1] = fma2(pp, v1, acc2[7][1]);
                acc2[7][2] = fma2(pp, v2, acc2[7][2]); acc2[7][3] = fma2(pp, v3, acc2[7][3]);
            }
        }
        __syncthreads();  // protect sK/sV/sS/sRed before next chunk
    }

    // Finalize: o[q][v] = acc / L[q]; write g_attn[b][v][n0+q]
    float o[8][8];
#pragma unroll
    for (int i = 0; i < 8; i++) {
        float inv = 1.f / s.sL[tq2 * 8 + i];
#pragma unroll
        for (int j = 0; j < 4; j++) {
            float lo, hi;
            unpack2(acc2[i][j], lo, hi);
            o[i][2 * j] = lo * inv;
            o[i][2 * j + 1] = hi * inv;
        }
    }
#pragma unroll
    for (int vloc = 0; vloc < 8; vloc++) {
        int v = tv * 8 + vloc;
        size_t base = ((size_t)(b * CV_ + v)) * N_PIX + n0 + tq2 * 8;
        float4 w0, w1;
        w0.x = o[0][vloc]; w0.y = o[1][vloc]; w0.z = o[2][vloc]; w0.w = o[3][vloc];
        w1.x = o[4][vloc]; w1.y = o[5][vloc]; w1.z = o[6][vloc]; w1.w = o[7][vloc];
        *reinterpret_cast<float4*>(&g_attn[base]) = w0;
        *reinterpret_cast<float4*>(&g_attn[base + 4]) = w1;
    }
}

// ---------------------------------------------------------------------------
// Host launcher.  Inputs: hidden, Wq, Wk, Wv, Wo, bo, gating
// ---------------------------------------------------------------------------
extern "C" void kernel_launch(void* const* d_in, const int* in_sizes, int n_in,
                              void* d_out, int out_size)
{
    const float* hidden = (const float*)d_in[0];
    const float* Wq = (const float*)d_in[1];
    const float* Wk = (const float*)d_in[2];
    const float* Wv = (const float*)d_in[3];
    const float* Wo = (const float*)d_in[4];
    const float* bo = (const float*)d_in[5];
    const float* gating = (const float*)d_in[6];
    float* out = (float*)d_out;

    float *pq = nullptr, *pkp = nullptr, *pvp = nullptr, *pattn = nullptr;
    cudaGetSymbolAddress((void**)&pq, g_q);
    cudaGetSymbolAddress((void**)&pkp, g_kp);
    cudaGetSymbolAddress((void**)&pvp, g_vp);
    cudaGetSymbolAddress((void**)&pattn, g_attn);

    dim3 blk(256);

    // q = Wq @ x                               [B,64,4096]
    gemm_kernel<false, false, false><<<dim3(32, 1, BATCH_), blk>>>(
        Wq, hidden, pq, CQK_, CH_, nullptr, nullptr, nullptr);
    // kp = pool2(Wk @ x)                       [B,64,1024] d-major
    gemm_kernel<true, false, false><<<dim3(32, 1, BATCH_), blk>>>(
        Wk, hidden, pkp, CQK_, CH_, nullptr, nullptr, nullptr);
    // vp = pool2(Wv @ x), transposed           [B,1024,256] m-major
    gemm_kernel<true, false, true><<<dim3(32, 4, BATCH_), blk>>>(
        Wv, hidden, pvp, CV_, CH_, nullptr, nullptr, nullptr);

    // attn = softmax(q^T kp) @ vp              [B,256,4096]
    cudaFuncSetAttribute(attn_kernel, cudaFuncAttributeMaxDynamicSharedMemorySize,
                         (int)sizeof(AttnSmem));
    attn_kernel<<<dim3(64, BATCH_), blk, sizeof(AttnSmem)>>>();

    // out = hidden + gating * (Wo @ attn + bo)
    gemm_kernel<false, true, false><<<dim3(32, 8, BATCH_), blk>>>(
        Wo, pattn, out, CH_, CV_, hidden, bo, gating);
}

// round 4
// speedup vs baseline: 2.2611x; 1.4059x over previous
#include <cuda_runtime.h>
#include <math.h>

typedef unsigned long long u64;

#define N_PIX 4096   // H*W = 64*64
#define M_POOL 1024
#define CQK_ 64
#define CV_ 256
#define CH_ 512
#define BATCH_ 16

__device__ float g_q[BATCH_ * CQK_ * N_PIX];     // [B,64,4096]
__device__ float g_kp[BATCH_ * CQK_ * M_POOL];   // [B,64,1024]  d-major
__device__ float g_vp[BATCH_ * M_POOL * CV_];    // [B,1024,256] m-major
__device__ float g_attn[BATCH_ * CV_ * N_PIX];   // [B,256,4096]

// ---- packed f32x2 helpers (Blackwell FFMA2 path) ----
__device__ __forceinline__ u64 pack2(float lo, float hi) {
    u64 r; asm("mov.b64 %0, {%1, %2};" : "=l"(r) : "f"(lo), "f"(hi)); return r;
}
__device__ __forceinline__ void unpack2(u64 v, float& lo, float& hi) {
    asm("mov.b64 {%0, %1}, %2;" : "=f"(lo), "=f"(hi) : "l"(v));
}
__device__ __forceinline__ u64 fma2(u64 a, u64 b, u64 c) {
    u64 d; asm("fma.rn.f32x2 %0, %1, %2, %3;" : "=l"(d) : "l"(a), "l"(b), "l"(c)); return d;
}
__device__ __forceinline__ u64 mul2(u64 a, u64 b) {
    u64 d; asm("mul.rn.f32x2 %0, %1, %2;" : "=l"(d) : "l"(a), "l"(b)); return d;
}

// ---------------------------------------------------------------------------
// Tiled SGEMM: out[b] = W[R,K] @ X[b][K, 4096]
// Tile 64m x 256n x 16k, 256 threads, microtile 8m x 8n (split n: tx*4 and
// 128+tx*4 for conflict-free LDS.128). Register-prefetch pipeline.
//  POOL   : 2x2-maxpool epilogue (BN=256 == 4 image rows -> 2 pooled rows)
//  TRANSP : pooled output m-major [B, M_POOL, R]
//  RESID  : d_out = hidden + gating*(acc + bo[r])
// ---------------------------------------------------------------------------
template <bool POOL, bool RESID, bool TRANSP>
__global__ __launch_bounds__(256) void gemm_kernel(
    const float* __restrict__ W, const float* __restrict__ X,
    float* __restrict__ out, int R, int K,
    const float* __restrict__ hidden, const float* __restrict__ bo,
    const float* __restrict__ gating)
{
    constexpr int BN = 256, BK = 16;
    __shared__ float sA[BK][72];                 // [k][m]
    __shared__ float sB[BK][BN];                 // [k][n]
    __shared__ float sC[POOL ? 64 : 1][POOL ? 261 : 1];

    const int b  = blockIdx.z;
    const int n0 = blockIdx.x * BN;
    const int m0 = blockIdx.y * 64;
    const int tid = threadIdx.x;
    const int tx = tid & 31;       // n-group: cols tx*4 and 128+tx*4
    const int ty = tid >> 5;       // m-group: rows ty*8 .. +7

    const float* __restrict__ Xb = X + (size_t)b * K * N_PIX;

    u64 acc2[8][4];                // [m][npair]: 0,1 -> tx*4; 2,3 -> 128+tx*4
#pragma unroll
    for (int i = 0; i < 8; i++)
#pragma unroll
        for (int j = 0; j < 4; j++) acc2[i][j] = 0ull;

    // prologue: tile k0=0
    {
        int r = tid >> 2, c4 = tid & 3;
        float4 v = *reinterpret_cast<const float4*>(&W[(size_t)(m0 + r) * K + c4 * 4]);
        sA[c4 * 4 + 0][r] = v.x; sA[c4 * 4 + 1][r] = v.y;
        sA[c4 * 4 + 2][r] = v.z; sA[c4 * 4 + 3][r] = v.w;
#pragma unroll
        for (int i = 0; i < 4; i++) {
            int idx = tid + i * 256;
            int kr = idx >> 6, c = idx & 63;
            *reinterpret_cast<float4*>(&sB[kr][c * 4]) =
                *reinterpret_cast<const float4*>(&Xb[(size_t)kr * N_PIX + n0 + c * 4]);
        }
    }
    __syncthreads();

#pragma unroll 1
    for (int k0 = 0; k0 < K; k0 += BK) {
        const bool has_next = (k0 + BK) < K;
        float4 rA;
        float4 rB[4];
        if (has_next) {
            const int k1 = k0 + BK;
            int r = tid >> 2, c4 = tid & 3;
            rA = *reinterpret_cast<const float4*>(&W[(size_t)(m0 + r) * K + k1 + c4 * 4]);
#pragma unroll
            for (int i = 0; i < 4; i++) {
                int idx = tid + i * 256;
                int kr = idx >> 6, c = idx & 63;
                rB[i] = *reinterpret_cast<const float4*>(
                    &Xb[(size_t)(k1 + kr) * N_PIX + n0 + c * 4]);
            }
        }

#pragma unroll
        for (int k = 0; k < BK; k++) {
            float4 a0 = *reinterpret_cast<const float4*>(&sA[k][ty * 8]);
            float4 a1 = *reinterpret_cast<const float4*>(&sA[k][ty * 8 + 4]);
            const u64* pb0 = reinterpret_cast<const u64*>(&sB[k][tx * 4]);
            const u64* pb1 = reinterpret_cast<const u64*>(&sB[k][128 + tx * 4]);
            u64 b0 = pb0[0], b1 = pb0[1], b2 = pb1[0], b3 = pb1[1];
            float am[8] = {a0.x, a0.y, a0.z, a0.w, a1.x, a1.y, a1.z, a1.w};
#pragma unroll
            for (int m = 0; m < 8; m++) {
                u64 as = pack2(am[m], am[m]);
                acc2[m][0] = fma2(as, b0, acc2[m][0]);
                acc2[m][1] = fma2(as, b1, acc2[m][1]);
                acc2[m][2] = fma2(as, b2, acc2[m][2]);
                acc2[m][3] = fma2(as, b3, acc2[m][3]);
            }
        }

        if (has_next) {
            __syncthreads();
            {
                int r = tid >> 2, c4 = tid & 3;
                sA[c4 * 4 + 0][r] = rA.x; sA[c4 * 4 + 1][r] = rA.y;
                sA[c4 * 4 + 2][r] = rA.z; sA[c4 * 4 + 3][r] = rA.w;
#pragma unroll
                for (int i = 0; i < 4; i++) {
                    int idx = tid + i * 256;
                    int kr = idx >> 6, c = idx & 63;
                    *reinterpret_cast<float4*>(&sB[kr][c * 4]) = rB[i];
                }
            }
            __syncthreads();
        }
    }

    // unpack: acc[m][col]; col 0..3 -> n = tx*4+col; col 4..7 -> 128+tx*4+(col-4)
    float acc[8][8];
#pragma unroll
    for (int m = 0; m < 8; m++) {
        unpack2(acc2[m][0], acc[m][0], acc[m][1]);
        unpack2(acc2[m][1], acc[m][2], acc[m][3]);
        unpack2(acc2[m][2], acc[m][4], acc[m][5]);
        unpack2(acc2[m][3], acc[m][6], acc[m][7]);
    }

    if (POOL) {
        __syncthreads();
#pragma unroll
        for (int m = 0; m < 8; m++) {
#pragma unroll
            for (int c = 0; c < 4; c++) sC[ty * 8 + m][tx * 4 + c] = acc[m][c];
#pragma unroll
            for (int c = 0; c < 4; c++) sC[ty * 8 + m][128 + tx * 4 + c] = acc[m][4 + c];
        }
        __syncthreads();
        // tile covers image rows 4*bx..4*bx+3 -> pooled rows 2*bx, 2*bx+1
        const int pr0 = blockIdx.x * 2;
#pragma unroll
        for (int i = 0; i < 16; i++) {
            int idx = tid + i * 256;             // 4096 outputs: 64 r x 64 (pr,j)
            int r, ml;
            if (TRANSP) { r = idx & 63; ml = idx >> 6; }
            else        { r = idx >> 6; ml = idx & 63; }
            int pr = ml >> 5, j = ml & 31;
            int base = pr * 128 + 2 * j;
            float v = fmaxf(fmaxf(sC[r][base], sC[r][base + 1]),
                            fmaxf(sC[r][base + 64], sC[r][base + 65]));
            int m = (pr0 + pr) * 32 + j;
            if (TRANSP)
                out[((size_t)b * M_POOL + m) * CV_ + m0 + r] = v;
            else
                out[((size_t)(b * R + m0 + r)) * M_POOL + m] = v;
        }
    } else if (RESID) {
        const float g = gating[0];
#pragma unroll
        for (int m = 0; m < 8; m++) {
            int r = m0 + ty * 8 + m;
            float bias = bo[r];
            size_t base = ((size_t)(b * R + r)) * N_PIX + n0 + tx * 4;
#pragma unroll
            for (int h = 0; h < 2; h++) {
                size_t a = base + h * 128;
                float4 hv = *reinterpret_cast<const float4*>(&hidden[a]);
                float4 w;
                w.x = hv.x + g * (acc[m][4 * h + 0] + bias);
                w.y = hv.y + g * (acc[m][4 * h + 1] + bias);
                w.z = hv.z + g * (acc[m][4 * h + 2] + bias);
                w.w = hv.w + g * (acc[m][4 * h + 3] + bias);
                *reinterpret_cast<float4*>(&out[a]) = w;
            }
        }
    } else {
#pragma unroll
        for (int m = 0; m < 8; m++) {
            size_t base = ((size_t)(b * R + m0 + ty * 8 + m)) * N_PIX + n0 + tx * 4;
            float4 w0, w1;
            w0.x = acc[m][0]; w0.y = acc[m][1]; w0.z = acc[m][2]; w0.w = acc[m][3];
            w1.x = acc[m][4]; w1.y = acc[m][5]; w1.z = acc[m][6]; w1.w = acc[m][7];
            *reinterpret_cast<float4*>(&out[base]) = w0;
            *reinterpret_cast<float4*>(&out[base + 128]) = w1;
        }
    }
}

// ---------------------------------------------------------------------------
// Flash attention: block = (batch b, 128 queries), 512 threads.
// 16 chunks of 64 keys, online softmax, S transposed [k][q], V [k][v].
// PV: 8q x 8v register microtile per thread.
// ---------------------------------------------------------------------------
struct __align__(16) AttnSmem {
    float sQ[64][132];   // [d][q]
    float sK[64][68];    // [d][k]
    float sS[64][132];   // [k][q]
    float sV[64][260];   // [k][v]
    float sRed[4][128];
    float sM[128];
    float sL[128];
    float sAlpha[128];
};

extern __shared__ char attn_smem_raw[];

__global__ __launch_bounds__(512) void attn_kernel()
{
    AttnSmem& s = *reinterpret_cast<AttnSmem*>(attn_smem_raw);
    const int b  = blockIdx.y;
    const int n0 = blockIdx.x * 128;
    const int tid = threadIdx.x;
    const int tq = tid & 31, tk = tid >> 5;    // S: 4q x 4k (32 x 16 groups)
    const int tq2 = tid & 15, tv = tid >> 4;   // PV: 8q x 8v (16 x 32 groups)
    const int row = tid & 127, seg = tid >> 7; // softmax: 128 rows x 4 segs

    // Q tile [64 d][128 q]
#pragma unroll
    for (int i = 0; i < 4; i++) {
        int idx = tid + i * 512;
        int d = idx >> 5, q4 = idx & 31;
        *reinterpret_cast<float4*>(&s.sQ[d][q4 * 4]) =
            *reinterpret_cast<const float4*>(&g_q[((size_t)(b * CQK_ + d)) * N_PIX + n0 + q4 * 4]);
    }
    if (tid < 128) { s.sM[tid] = -1e30f; s.sL[tid] = 0.f; }

    u64 acc2[8][4];
#pragma unroll
    for (int i = 0; i < 8; i++)
#pragma unroll
        for (int j = 0; j < 4; j++) acc2[i][j] = 0ull;
    __syncthreads();

#pragma unroll 1
    for (int ch = 0; ch < 16; ch++) {
        const int mm0 = ch * 64;
        // K chunk [64 d][64 k]
#pragma unroll
        for (int i = 0; i < 2; i++) {
            int idx = tid + i * 512;
            int d = idx >> 4, k4 = idx & 15;
            *reinterpret_cast<float4*>(&s.sK[d][k4 * 4]) =
                *reinterpret_cast<const float4*>(&g_kp[((size_t)(b * CQK_ + d)) * M_POOL + mm0 + k4 * 4]);
        }
        // V chunk [64 k][256 v]
#pragma unroll
        for (int i = 0; i < 8; i++) {
            int idx = tid + i * 512;
            int kk = idx >> 6, v4 = idx & 63;
            *reinterpret_cast<float4*>(&s.sV[kk][v4 * 4]) =
                *reinterpret_cast<const float4*>(&g_vp[((size_t)b * M_POOL + mm0 + kk) * CV_ + v4 * 4]);
        }
        __syncthreads();

        // S = Q^T K (4q x 4k per thread)
        {
            u64 sc2[4][2];
#pragma unroll
            for (int i = 0; i < 4; i++) { sc2[i][0] = 0ull; sc2[i][1] = 0ull; }
#pragma unroll 8
            for (int d = 0; d < 64; d++) {
                float4 a = *reinterpret_cast<const float4*>(&s.sQ[d][tq * 4]);
                const u64* pb = reinterpret_cast<const u64*>(&s.sK[d][tk * 4]);
                u64 b0 = pb[0], b1 = pb[1];
                u64 a0 = pack2(a.x, a.x), a1 = pack2(a.y, a.y);
                u64 a2 = pack2(a.z, a.z), a3 = pack2(a.w, a.w);
                sc2[0][0] = fma2(a0, b0, sc2[0][0]); sc2[0][1] = fma2(a0, b1, sc2[0][1]);
                sc2[1][0] = fma2(a1, b0, sc2[1][0]); sc2[1][1] = fma2(a1, b1, sc2[1][1]);
                sc2[2][0] = fma2(a2, b0, sc2[2][0]); sc2[2][1] = fma2(a2, b1, sc2[2][1]);
                sc2[3][0] = fma2(a3, b0, sc2[3][0]); sc2[3][1] = fma2(a3, b1, sc2[3][1]);
            }
#pragma unroll
            for (int i = 0; i < 4; i++)
#pragma unroll
                for (int jp = 0; jp < 2; jp++) {
                    float lo, hi;
                    unpack2(sc2[i][jp], lo, hi);
                    s.sS[tk * 4 + 2 * jp][tq * 4 + i] = lo;
                    s.sS[tk * 4 + 2 * jp + 1][tq * 4 + i] = hi;
                }
        }
        __syncthreads();

        // online softmax over 64 keys (column access, conflict-free)
        float pm = -1e30f;
#pragma unroll
        for (int j = 0; j < 16; j++) pm = fmaxf(pm, s.sS[seg * 16 + j][row]);
        s.sRed[seg][row] = pm;
        __syncthreads();
        if (tid < 128) {
            float mc = fmaxf(fmaxf(s.sRed[0][tid], s.sRed[1][tid]),
                             fmaxf(s.sRed[2][tid], s.sRed[3][tid]));
            float mn = fmaxf(s.sM[tid], mc);
            s.sAlpha[tid] = __expf(s.sM[tid] - mn);
            s.sM[tid] = mn;
        }
        __syncthreads();
        {
            float mn = s.sM[row];
            float ps = 0.f;
#pragma unroll
            for (int j = 0; j < 16; j++) {
                float p = __expf(s.sS[seg * 16 + j][row] - mn);
                s.sS[seg * 16 + j][row] = p;
                ps += p;
            }
            s.sRed[seg][row] = ps;
        }
        __syncthreads();
        if (tid < 128) {
            s.sL[tid] = s.sL[tid] * s.sAlpha[tid] +
                        (s.sRed[0][tid] + s.sRed[1][tid] + s.sRed[2][tid] + s.sRed[3][tid]);
        }

        // rescale, then O += P^T V  (8q x 8v)
        {
#pragma unroll
            for (int i = 0; i < 8; i++) {
                float a = s.sAlpha[tq2 * 8 + i];
                u64 ap = pack2(a, a);
#pragma unroll
                for (int j = 0; j < 4; j++) acc2[i][j] = mul2(acc2[i][j], ap);
            }
#pragma unroll 4
            for (int k = 0; k < 64; k++) {
                float4 p0 = *reinterpret_cast<const float4*>(&s.sS[k][tq2 * 8]);
                float4 p1 = *reinterpret_cast<const float4*>(&s.sS[k][tq2 * 8 + 4]);
                const u64* pv = reinterpret_cast<const u64*>(&s.sV[k][tv * 8]);
                u64 v0 = pv[0], v1 = pv[1], v2 = pv[2], v3 = pv[3];
                float pm8[8] = {p0.x, p0.y, p0.z, p0.w, p1.x, p1.y, p1.z, p1.w};
#pragma unroll
                for (int i = 0; i < 8; i++) {
                    u64 pp = pack2(pm8[i], pm8[i]);
                    acc2[i][0] = fma2(pp, v0, acc2[i][0]);
                    acc2[i][1] = fma2(pp, v1, acc2[i][1]);
                    acc2[i][2] = fma2(pp, v2, acc2[i][2]);
                    acc2[i][3] = fma2(pp, v3, acc2[i][3]);
                }
            }
        }
        __syncthreads();
    }

    // finalize: o = acc / L[q]; write g_attn[b][v][n0+q]
    float o[8][8];
#pragma unroll
    for (int i = 0; i < 8; i++) {
        float inv = 1.f / s.sL[tq2 * 8 + i];
#pragma unroll
        for (int j = 0; j < 4; j++) {
            float lo, hi;
            unpack2(acc2[i][j], lo, hi);
            o[i][2 * j] = lo * inv;
            o[i][2 * j + 1] = hi * inv;
        }
    }
#pragma unroll
    for (int vloc = 0; vloc < 8; vloc++) {
        int v = tv * 8 + vloc;
        size_t base = ((size_t)(b * CV_ + v)) * N_PIX + n0 + tq2 * 8;
        float4 w0, w1;
        w0.x = o[0][vloc]; w0.y = o[1][vloc]; w0.z = o[2][vloc]; w0.w = o[3][vloc];
        w1.x = o[4][vloc]; w1.y = o[5][vloc]; w1.z = o[6][vloc]; w1.w = o[7][vloc];
        *reinterpret_cast<float4*>(&g_attn[base]) = w0;
        *reinterpret_cast<float4*>(&g_attn[base + 4]) = w1;
    }
}

// ---------------------------------------------------------------------------
// Host launcher.  Inputs: hidden, Wq, Wk, Wv, Wo, bo, gating
// ---------------------------------------------------------------------------
extern "C" void kernel_launch(void* const* d_in, const int* in_sizes, int n_in,
                              void* d_out, int out_size)
{
    const float* hidden = (const float*)d_in[0];
    const float* Wq = (const float*)d_in[1];
    const float* Wk = (const float*)d_in[2];
    const float* Wv = (const float*)d_in[3];
    const float* Wo = (const float*)d_in[4];
    const float* bo = (const float*)d_in[5];
    const float* gating = (const float*)d_in[6];
    float* out = (float*)d_out;

    float *pq = nullptr, *pkp = nullptr, *pvp = nullptr, *pattn = nullptr;
    cudaGetSymbolAddress((void**)&pq, g_q);
    cudaGetSymbolAddress((void**)&pkp, g_kp);
    cudaGetSymbolAddress((void**)&pvp, g_vp);
    cudaGetSymbolAddress((void**)&pattn, g_attn);

    dim3 blk(256);

    // q = Wq @ x                               [B,64,4096]
    gemm_kernel<false, false, false><<<dim3(16, 1, BATCH_), blk>>>(
        Wq, hidden, pq, CQK_, CH_, nullptr, nullptr, nullptr);
    // kp = pool2(Wk @ x)                       [B,64,1024] d-major
    gemm_kernel<true, false, false><<<dim3(16, 1, BATCH_), blk>>>(
        Wk, hidden, pkp, CQK_, CH_, nullptr, nullptr, nullptr);
    // vp = pool2(Wv @ x), transposed           [B,1024,256] m-major
    gemm_kernel<true, false, true><<<dim3(16, 4, BATCH_), blk>>>(
        Wv, hidden, pvp, CV_, CH_, nullptr, nullptr, nullptr);

    // attn = softmax(q^T kp) @ vp              [B,256,4096]
    cudaFuncSetAttribute(attn_kernel, cudaFuncAttributeMaxDynamicSharedMemorySize,
                         (int)sizeof(AttnSmem));
    attn_kernel<<<dim3(32, BATCH_), dim3(512), sizeof(AttnSmem)>>>();

    // out = hidden + gating * (Wo @ attn + bo)
    gemm_kernel<false, true, false><<<dim3(16, 8, BATCH_), blk>>>(
        Wo, pattn, out, CH_, CV_, hidden, bo, gating);
}

// round 13
// speedup vs baseline: 2.7072x; 1.1973x over previous
#include <cuda_runtime.h>
#include <cuda_bf16.h>
#include <math.h>
#include <stdint.h>

typedef unsigned long long u64;

#define N_PIX 4096
#define M_POOL 1024
#define CQK_ 64
#define CV_ 256
#define CH_ 512
#define BATCH_ 16

// ---------------- scratch ----------------
__device__ __align__(16) float g_q[BATCH_ * CQK_ * N_PIX];      // [B,64,4096]
__device__ __align__(16) float g_kp[BATCH_ * CQK_ * M_POOL];    // [B,64,1024]
__device__ __align__(16) float g_vp[BATCH_ * M_POOL * CV_];     // [B,1024,256]
__device__ __align__(16) __nv_bfloat16 g_hT0[BATCH_ * N_PIX * CH_];  // hidden^T hi
__device__ __align__(16) __nv_bfloat16 g_hT1[BATCH_ * N_PIX * CH_];  // lo
__device__ __align__(16) __nv_bfloat16 g_at0[BATCH_ * N_PIX * CV_];  // attn^T hi
__device__ __align__(16) __nv_bfloat16 g_at1[BATCH_ * N_PIX * CV_];
__device__ __align__(16) __nv_bfloat16 g_wqk0[128 * CH_], g_wqk1[128 * CH_];
__device__ __align__(16) __nv_bfloat16 g_wv0[CV_ * CH_], g_wv1[CV_ * CH_];
__device__ __align__(16) __nv_bfloat16 g_wo0[CH_ * CV_], g_wo1[CH_ * CV_];

// ---------------- packed f32x2 helpers (attention) ----------------
__device__ __forceinline__ u64 pack2(float lo, float hi) {
    u64 r; asm("mov.b64 %0, {%1, %2};" : "=l"(r) : "f"(lo), "f"(hi)); return r;
}
__device__ __forceinline__ void unpack2(u64 v, float& lo, float& hi) {
    asm("mov.b64 {%0, %1}, %2;" : "=f"(lo), "=f"(hi) : "l"(v));
}
__device__ __forceinline__ u64 fma2(u64 a, u64 b, u64 c) {
    u64 d; asm("fma.rn.f32x2 %0, %1, %2, %3;" : "=l"(d) : "l"(a), "l"(b), "l"(c)); return d;
}
__device__ __forceinline__ u64 mul2(u64 a, u64 b) {
    u64 d; asm("mul.rn.f32x2 %0, %1, %2;" : "=l"(d) : "l"(a), "l"(b)); return d;
}

// ---------------- mma.sync helpers (sm_80+ baseline; NOT arch-'a') ----------
__device__ __forceinline__ uint32_t smem_u32(const void* p) {
    uint32_t a;
    asm("{ .reg .u64 t; cvta.to.shared.u64 t, %1; cvt.u32.u64 %0, t; }" : "=r"(a) : "l"(p));
    return a;
}
__device__ __forceinline__ void ldsm_x4(uint32_t* r, uint32_t addr) {
    asm volatile("ldmatrix.sync.aligned.m8n8.x4.shared.b16 {%0,%1,%2,%3}, [%4];"
                 : "=r"(r[0]), "=r"(r[1]), "=r"(r[2]), "=r"(r[3]) : "r"(addr));
}
__device__ __forceinline__ void mma_bf16(float* c, const uint32_t* a, uint32_t b0, uint32_t b1) {
    asm volatile("mma.sync.aligned.m16n8k16.row.col.f32.bf16.bf16.f32 "
                 "{%0,%1,%2,%3}, {%4,%5,%6,%7}, {%8,%9}, {%0,%1,%2,%3};"
                 : "+f"(c[0]), "+f"(c[1]), "+f"(c[2]), "+f"(c[3])
                 : "r"(a[0]), "r"(a[1]), "r"(a[2]), "r"(a[3]), "r"(b0), "r"(b1));
}
__device__ __forceinline__ void cp16(uint32_t smem_dst, const void* gsrc) {
    asm volatile("cp.async.cg.shared.global [%0], [%1], 16;" :: "r"(smem_dst), "l"(gsrc));
}

// ---------------------------------------------------------------------------
// Conversion kernels
// ---------------------------------------------------------------------------
__global__ __launch_bounds__(256) void convert_w_kernel(
    const float* __restrict__ Wq, const float* __restrict__ Wk,
    const float* __restrict__ Wv, const float* __restrict__ Wo)
{
    int idx = blockIdx.x * 256 + threadIdx.x;
    float x; __nv_bfloat16 *d0, *d1; int off;
    if (idx < 65536) {                       // wqk: [128][512]
        int r = idx >> 9, c = idx & 511;
        x = (r < 64) ? Wq[r * 512 + c] : Wk[(r - 64) * 512 + c];
        d0 = g_wqk0; d1 = g_wqk1; off = idx;
    } else if (idx < 196608) {               // wv: [256][512]
        off = idx - 65536; x = Wv[off]; d0 = g_wv0; d1 = g_wv1;
    } else {                                 // wo: [512][256]
        off = idx - 196608; x = Wo[off]; d0 = g_wo0; d1 = g_wo1;
    }
    __nv_bfloat16 h = __float2bfloat16(x);
    __nv_bfloat16 l = __float2bfloat16(x - __bfloat162float(h));
    d0[off] = h; d1[off] = l;
}

// hidden [B,512,4096] -> transposed splits [B,4096,512]
__global__ __launch_bounds__(256) void convert_h_kernel(const float* __restrict__ hidden)
{
    __shared__ float t[64][65];
    const int p0 = blockIdx.x * 64, ch0 = blockIdx.y * 64, b = blockIdx.z;
    const int tid = threadIdx.x;
#pragma unroll
    for (int i = 0; i < 16; i++) {
        int idx = tid + i * 256;
        int r = idx >> 6, c = idx & 63;
        t[r][c] = hidden[((size_t)(b * CH_ + ch0 + r)) * N_PIX + p0 + c];
    }
    __syncthreads();
#pragma unroll
    for (int i = 0; i < 16; i++) {
        int idx = tid + i * 256;
        int ch = idx & 63, p = idx >> 6;
        float x = t[ch][p];
        __nv_bfloat16 h = __float2bfloat16(x);
        __nv_bfloat16 l = __float2bfloat16(x - __bfloat162float(h));
        size_t a = ((size_t)(b * N_PIX + p0 + p)) * CH_ + ch0 + ch;
        g_hT0[a] = h; g_hT1[a] = l;
    }
}

// ---------------------------------------------------------------------------
// mma.sync GEMM: D[128ch][256pix] = Wsplit @ Xsplit^T, 3-term bf16 split.
// 512 thr = 16 warps (4m x 4n), warp tile 32x64, K-chunk 32, cp.async
// double-buffered smem (pitch 80B, conflict-free ldmatrix).
//   VAR 0 = QK (q store + k pool), 1 = V (pool+transpose), 2 = OUT (residual)
// Chunk buffer layout (61440B each): A0 10240 | A1 10240 | B0 20480 | B1 20480.
// Epilogue stages D into the same region: stg[128][260] fp32 (133120B).
// ---------------------------------------------------------------------------
extern __shared__ char mma_smem[];

template <int VAR>
__global__ __launch_bounds__(512)
void mma_gemm_kernel(const float* __restrict__ hidden, const float* __restrict__ bo,
                     const float* __restrict__ gating, float* __restrict__ dout)
{
    constexpr int KD = (VAR == 2) ? 256 : 512;
    constexpr int NCH = KD / 32;
    constexpr int BUF = 61440;

    const int b  = blockIdx.z;
    const int my = blockIdx.y;
    const int bx = blockIdx.x;
    const int n0 = bx * 256;
    const int tid = threadIdx.x;
    const int wid = tid >> 5, lane = tid & 31;
    const int wm = wid >> 2, wn = wid & 3;

    const uint32_t sb = smem_u32(mma_smem);

    const __nv_bfloat16 *A0, *A1, *B0, *B1;
    if (VAR == 0)      { A0 = g_wqk0; A1 = g_wqk1; B0 = g_hT0; B1 = g_hT1; }
    else if (VAR == 1) { A0 = g_wv0 + (size_t)my * 128 * KD; A1 = g_wv1 + (size_t)my * 128 * KD;
                         B0 = g_hT0; B1 = g_hT1; }
    else               { A0 = g_wo0 + (size_t)my * 128 * KD; A1 = g_wo1 + (size_t)my * 128 * KD;
                         B0 = g_at0; B1 = g_at1; }
    const size_t brow0 = (size_t)b * N_PIX + n0;

    float acc[2][8][4];
#pragma unroll
    for (int i = 0; i < 2; i++)
#pragma unroll
        for (int j = 0; j < 8; j++)
#pragma unroll
            for (int r = 0; r < 4; r++) acc[i][j][r] = 0.f;

    // ---- async load of one K-chunk into buffer `bufi` ----
    auto issue_chunk = [&](int c, int bufi) {
        const uint32_t base = sb + bufi * BUF;
#pragma unroll
        for (int i = 0; i < 2; i++) {          // A: 1024 x 16B
            int idx = tid + i * 512;
            int sp = idx >> 9, rem = idx & 511;
            int row = rem >> 2, q = rem & 3;
            cp16(base + sp * 10240 + row * 80 + q * 16,
                 (sp ? A1 : A0) + (size_t)row * KD + c * 32 + q * 8);
        }
#pragma unroll
        for (int i = 0; i < 4; i++) {          // B: 2048 x 16B
            int idx = tid + i * 512;
            int sp = idx >> 10, rem = idx & 1023;
            int row = rem >> 2, q = rem & 3;
            cp16(base + 20480 + sp * 20480 + row * 80 + q * 16,
                 (sp ? B1 : B0) + (brow0 + row) * KD + c * 32 + q * 8);
        }
    };

    issue_chunk(0, 0);
    asm volatile("cp.async.commit_group;" ::: "memory");

#pragma unroll 1
    for (int c = 0; c < NCH; c++) {
        if (c + 1 < NCH) {
            issue_chunk(c + 1, (c + 1) & 1);
            asm volatile("cp.async.commit_group;" ::: "memory");
            asm volatile("cp.async.wait_group 1;" ::: "memory");
        } else {
            asm volatile("cp.async.wait_group 0;" ::: "memory");
        }
        __syncthreads();

        const uint32_t base = sb + (c & 1) * BUF;
#pragma unroll
        for (int ks = 0; ks < 2; ks++) {
            const int kb = ks * 32;             // 16 bf16 = 32B
            const uint32_t lrow = (lane & 15);
            const uint32_t lcol = (lane >> 4) << 4;
            uint32_t aF[2][2][4];
#pragma unroll
            for (int sp = 0; sp < 2; sp++)
#pragma unroll
                for (int mt = 0; mt < 2; mt++)
                    ldsm_x4(aF[sp][mt],
                            base + sp * 10240 + (wm * 32 + mt * 16 + lrow) * 80 + kb + lcol);
#pragma unroll
            for (int ng = 0; ng < 4; ng++) {
                uint32_t bd = base + 20480 + (wn * 64 + ng * 16 + lrow) * 80 + kb + lcol;
                uint32_t bF0[4], bF1[4];
                ldsm_x4(bF0, bd);
                ldsm_x4(bF1, bd + 20480);
#pragma unroll
                for (int mt = 0; mt < 2; mt++)
#pragma unroll
                    for (int h = 0; h < 2; h++) {
                        float* cc = acc[mt][ng * 2 + h];
                        mma_bf16(cc, aF[0][mt], bF0[h], bF0[h + 2]);  // A0 B0
                        mma_bf16(cc, aF[0][mt], bF1[h], bF1[h + 2]);  // A0 B1
                        mma_bf16(cc, aF[1][mt], bF0[h], bF0[h + 2]);  // A1 B0
                    }
            }
        }
        __syncthreads();
    }

    // ---- stage D fragments -> stg[128][260] fp32 ----
    float* stg = reinterpret_cast<float*>(mma_smem);
    {
#pragma unroll
        for (int mt = 0; mt < 2; mt++)
#pragma unroll
            for (int j = 0; j < 8; j++) {
                int rr = wm * 32 + mt * 16 + (lane >> 2);
                int cc = wn * 64 + j * 8 + ((lane & 3) << 1);
                float2 lo = make_float2(acc[mt][j][0], acc[mt][j][1]);
                float2 hi = make_float2(acc[mt][j][2], acc[mt][j][3]);
                *reinterpret_cast<float2*>(&stg[rr * 260 + cc]) = lo;
                *reinterpret_cast<float2*>(&stg[(rr + 8) * 260 + cc]) = hi;
            }
    }
    __syncthreads();

    if (VAR == 0) {
        // q: rows 0-63 plain, coalesced float4 (4096 float4)
#pragma unroll
        for (int i = 0; i < 8; i++) {
            int idx4 = tid + i * 512;
            int ch = idx4 >> 6, p4 = idx4 & 63;
            float4 v = *reinterpret_cast<const float4*>(&stg[ch * 260 + p4 * 4]);
            *reinterpret_cast<float4*>(&g_q[((size_t)(b * CQK_ + ch)) * N_PIX + n0 + p4 * 4]) = v;
        }
        // k: rows 64-127, 2x2 pool (4096 outputs)
#pragma unroll
        for (int i = 0; i < 8; i++) {
            int idx = tid + i * 512;
            int j = idx & 31, pr = (idx >> 5) & 1, ch = idx >> 6;
            const float* r = &stg[(64 + ch) * 260 + pr * 128 + 2 * j];
            float v = fmaxf(fmaxf(r[0], r[1]), fmaxf(r[64], r[65]));
            int m = (2 * bx + pr) * 32 + j;
            g_kp[((size_t)(b * CQK_ + ch)) * M_POOL + m] = v;
        }
    } else if (VAR == 1) {
        // v: pool + transpose -> g_vp[b][m][ch] (8192 outputs)
#pragma unroll
        for (int i = 0; i < 16; i++) {
            int idx = tid + i * 512;
            int chl = idx & 127, pm = idx >> 7;
            int pr = pm >> 5, j = pm & 31;
            const float* r = &stg[chl * 260 + pr * 128 + 2 * j];
            float v = fmaxf(fmaxf(r[0], r[1]), fmaxf(r[64], r[65]));
            int m = (2 * bx + pr) * 32 + j;
            g_vp[((size_t)b * M_POOL + m) * CV_ + my * 128 + chl] = v;
        }
    } else {
        const float g = gating[0];
#pragma unroll
        for (int i = 0; i < 16; i++) {
            int idx4 = tid + i * 512;
            int ch = idx4 >> 6, p4 = idx4 & 63;
            int chg = my * 128 + ch;
            float bias = bo[chg];
            float4 dv = *reinterpret_cast<const float4*>(&stg[ch * 260 + p4 * 4]);
            size_t a = ((size_t)(b * CH_ + chg)) * N_PIX + n0 + p4 * 4;
            float4 h = *reinterpret_cast<const float4*>(&hidden[a]);
            float4 w;
            w.x = h.x + g * (dv.x + bias);
            w.y = h.y + g * (dv.y + bias);
            w.z = h.z + g * (dv.z + bias);
            w.w = h.w + g * (dv.w + bias);
            *reinterpret_cast<float4*>(&dout[a]) = w;
        }
    }
}

// ---------------------------------------------------------------------------
// Flash attention (SIMT, proven R4 compute): block = (b, 128 q), 512 threads.
// Output written as pixel-major bf16 SPLITS for the mma out-proj.
// ---------------------------------------------------------------------------
struct __align__(16) AttnSmem {
    float sQ[64][132];
    float sK[64][68];
    float sS[64][132];
    float sV[64][260];
    float sRed[4][128];
    float sM[128];
    float sL[128];
    float sAlpha[128];
};

extern __shared__ char attn_smem_raw[];

__global__ __launch_bounds__(512) void attn_kernel()
{
    AttnSmem& s = *reinterpret_cast<AttnSmem*>(attn_smem_raw);
    const int b  = blockIdx.y;
    const int n0 = blockIdx.x * 128;
    const int tid = threadIdx.x;
    const int tq = tid & 31, tk = tid >> 5;
    const int tq2 = tid & 15, tv = tid >> 4;
    const int row = tid & 127, seg = tid >> 7;

#pragma unroll
    for (int i = 0; i < 4; i++) {
        int idx = tid + i * 512;
        int d = idx >> 5, q4 = idx & 31;
        *reinterpret_cast<float4*>(&s.sQ[d][q4 * 4]) =
            *reinterpret_cast<const float4*>(&g_q[((size_t)(b * CQK_ + d)) * N_PIX + n0 + q4 * 4]);
    }
    if (tid < 128) { s.sM[tid] = -1e30f; s.sL[tid] = 0.f; }

    u64 acc2[8][4];
#pragma unroll
    for (int i = 0; i < 8; i++)
#pragma unroll
        for (int j = 0; j < 4; j++) acc2[i][j] = 0ull;
    __syncthreads();

#pragma unroll 1
    for (int ch = 0; ch < 16; ch++) {
        const int mm0 = ch * 64;
#pragma unroll
        for (int i = 0; i < 2; i++) {
            int idx = tid + i * 512;
            int d = idx >> 4, k4 = idx & 15;
            *reinterpret_cast<float4*>(&s.sK[d][k4 * 4]) =
                *reinterpret_cast<const float4*>(&g_kp[((size_t)(b * CQK_ + d)) * M_POOL + mm0 + k4 * 4]);
        }
#pragma unroll
        for (int i = 0; i < 8; i++) {
            int idx = tid + i * 512;
            int kk = idx >> 6, v4 = idx & 63;
            *reinterpret_cast<float4*>(&s.sV[kk][v4 * 4]) =
                *reinterpret_cast<const float4*>(&g_vp[((size_t)b * M_POOL + mm0 + kk) * CV_ + v4 * 4]);
        }
        __syncthreads();

        {
            u64 sc2[4][2];
#pragma unroll
            for (int i = 0; i < 4; i++) { sc2[i][0] = 0ull; sc2[i][1] = 0ull; }
#pragma unroll 8
            for (int d = 0; d < 64; d++) {
                float4 a = *reinterpret_cast<const float4*>(&s.sQ[d][tq * 4]);
                const u64* pb = reinterpret_cast<const u64*>(&s.sK[d][tk * 4]);
                u64 b0 = pb[0], b1 = pb[1];
                u64 a0 = pack2(a.x, a.x), a1 = pack2(a.y, a.y);
                u64 a2 = pack2(a.z, a.z), a3 = pack2(a.w, a.w);
                sc2[0][0] = fma2(a0, b0, sc2[0][0]); sc2[0][1] = fma2(a0, b1, sc2[0][1]);
                sc2[1][0] = fma2(a1, b0, sc2[1][0]); sc2[1][1] = fma2(a1, b1, sc2[1][1]);
                sc2[2][0] = fma2(a2, b0, sc2[2][0]); sc2[2][1] = fma2(a2, b1, sc2[2][1]);
                sc2[3][0] = fma2(a3, b0, sc2[3][0]); sc2[3][1] = fma2(a3, b1, sc2[3][1]);
            }
#pragma unroll
            for (int i = 0; i < 4; i++)
#pragma unroll
                for (int jp = 0; jp < 2; jp++) {
                    float lo, hi;
                    unpack2(sc2[i][jp], lo, hi);
                    s.sS[tk * 4 + 2 * jp][tq * 4 + i] = lo;
                    s.sS[tk * 4 + 2 * jp + 1][tq * 4 + i] = hi;
                }
        }
        __syncthreads();

        float pm = -1e30f;
#pragma unroll
        for (int j = 0; j < 16; j++) pm = fmaxf(pm, s.sS[seg * 16 + j][row]);
        s.sRed[seg][row] = pm;
        __syncthreads();
        if (tid < 128) {
            float mc = fmaxf(fmaxf(s.sRed[0][tid], s.sRed[1][tid]),
                             fmaxf(s.sRed[2][tid], s.sRed[3][tid]));
            float mn = fmaxf(s.sM[tid], mc);
            s.sAlpha[tid] = __expf(s.sM[tid] - mn);
            s.sM[tid] = mn;
        }
        __syncthreads();
        {
            float mn = s.sM[row];
            float ps = 0.f;
#pragma unroll
            for (int j = 0; j < 16; j++) {
                float p = __expf(s.sS[seg * 16 + j][row] - mn);
                s.sS[seg * 16 + j][row] = p;
                ps += p;
            }
            s.sRed[seg][row] = ps;
        }
        __syncthreads();
        if (tid < 128) {
            s.sL[tid] = s.sL[tid] * s.sAlpha[tid] +
                        (s.sRed[0][tid] + s.sRed[1][tid] + s.sRed[2][tid] + s.sRed[3][tid]);
        }

        {
#pragma unroll
            for (int i = 0; i < 8; i++) {
                float a = s.sAlpha[tq2 * 8 + i];
                u64 ap = pack2(a, a);
#pragma unroll
                for (int j = 0; j < 4; j++) acc2[i][j] = mul2(acc2[i][j], ap);
            }
#pragma unroll 4
            for (int k = 0; k < 64; k++) {
                float4 p0 = *reinterpret_cast<const float4*>(&s.sS[k][tq2 * 8]);
                float4 p1 = *reinterpret_cast<const float4*>(&s.sS[k][tq2 * 8 + 4]);
                const u64* pv = reinterpret_cast<const u64*>(&s.sV[k][tv * 8]);
                u64 v0 = pv[0], v1 = pv[1], v2 = pv[2], v3 = pv[3];
                float pm8[8] = {p0.x, p0.y, p0.z, p0.w, p1.x, p1.y, p1.z, p1.w};
#pragma unroll
                for (int i = 0; i < 8; i++) {
                    u64 pp = pack2(pm8[i], pm8[i]);
                    acc2[i][0] = fma2(pp, v0, acc2[i][0]);
                    acc2[i][1] = fma2(pp, v1, acc2[i][1]);
                    acc2[i][2] = fma2(pp, v2, acc2[i][2]);
                    acc2[i][3] = fma2(pp, v3, acc2[i][3]);
                }
            }
        }
        __syncthreads();
    }

    // finalize -> pixel-major bf16 splits g_at0/g_at1[b][pix][v]
#pragma unroll
    for (int i = 0; i < 8; i++) {
        float inv = 1.f / s.sL[tq2 * 8 + i];
        float o[8];
#pragma unroll
        for (int j = 0; j < 4; j++) {
            float lo, hi;
            unpack2(acc2[i][j], lo, hi);
            o[2 * j] = lo * inv;
            o[2 * j + 1] = hi * inv;
        }
        uint32_t h32[4], l32[4];
#pragma unroll
        for (int j = 0; j < 4; j++) {
            __nv_bfloat16 h0 = __float2bfloat16(o[2 * j]);
            __nv_bfloat16 h1 = __float2bfloat16(o[2 * j + 1]);
            __nv_bfloat16 l0 = __float2bfloat16(o[2 * j] - __bfloat162float(h0));
            __nv_bfloat16 l1 = __float2bfloat16(o[2 * j + 1] - __bfloat162float(h1));
            h32[j] = (uint32_t)__bfloat16_as_ushort(h0) | ((uint32_t)__bfloat16_as_ushort(h1) << 16);
            l32[j] = (uint32_t)__bfloat16_as_ushort(l0) | ((uint32_t)__bfloat16_as_ushort(l1) << 16);
        }
        size_t base = ((size_t)b * N_PIX + n0 + tq2 * 8 + i) * CV_ + tv * 8;
        *reinterpret_cast<uint4*>(&g_at0[base]) = make_uint4(h32[0], h32[1], h32[2], h32[3]);
        *reinterpret_cast<uint4*>(&g_at1[base]) = make_uint4(l32[0], l32[1], l32[2], l32[3]);
    }
}

// ---------------------------------------------------------------------------
// Host launcher.  Inputs: hidden, Wq, Wk, Wv, Wo, bo, gating
// ---------------------------------------------------------------------------
extern "C" void kernel_launch(void* const* d_in, const int* in_sizes, int n_in,
                              void* d_out, int out_size)
{
    const float* hidden = (const float*)d_in[0];
    const float* Wq = (const float*)d_in[1];
    const float* Wk = (const float*)d_in[2];
    const float* Wv = (const float*)d_in[3];
    const float* Wo = (const float*)d_in[4];
    const float* bo = (const float*)d_in[5];
    const float* gating = (const float*)d_in[6];
    float* out = (float*)d_out;

    const int MMA_SMEM = 133120;   // max(2 x 61440 mainloop, 128*260*4 stage)

    cudaFuncSetAttribute(mma_gemm_kernel<0>, cudaFuncAttributeMaxDynamicSharedMemorySize, MMA_SMEM);
    cudaFuncSetAttribute(mma_gemm_kernel<1>, cudaFuncAttributeMaxDynamicSharedMemorySize, MMA_SMEM);
    cudaFuncSetAttribute(mma_gemm_kernel<2>, cudaFuncAttributeMaxDynamicSharedMemorySize, MMA_SMEM);
    cudaFuncSetAttribute(attn_kernel, cudaFuncAttributeMaxDynamicSharedMemorySize, (int)sizeof(AttnSmem));

    // 1. input conversions
    convert_w_kernel<<<1280, 256>>>(Wq, Wk, Wv, Wo);
    convert_h_kernel<<<dim3(64, 8, BATCH_), 256>>>(hidden);

    // 2. q/k (fused, M=128) and v projections on tensor cores (mma.sync)
    mma_gemm_kernel<0><<<dim3(16, 1, BATCH_), 512, MMA_SMEM>>>(nullptr, nullptr, nullptr, nullptr);
    mma_gemm_kernel<1><<<dim3(16, 2, BATCH_), 512, MMA_SMEM>>>(nullptr, nullptr, nullptr, nullptr);

    // 3. attention (SIMT), emits bf16-split attn^T
    attn_kernel<<<dim3(32, BATCH_), dim3(512), sizeof(AttnSmem)>>>();

    // 4. output projection + residual on tensor cores
    mma_gemm_kernel<2><<<dim3(16, 4, BATCH_), 512, MMA_SMEM>>>(hidden, bo, gating, out);
}